// round 6
// baseline (speedup 1.0000x reference)
#include <cuda_runtime.h>

// Inputs (metadata order):
//   d_in[0] sample       int32  [B,3]      (head, rel, tail)
//   d_in[1] entity_emb   f32    [E,128]
//   d_in[2] relation_emb f32    [R,128]    (unused by the math)
//   d_in[3] type_emb     f32    [T*R, 128*128]
//   d_in[4] node_type    int32  [E]
// Output: f32 [B] scores.
//
// Algebra: score uses only he[0..2] -> 3 dot products per sample.
//
// Structure: each full-width warp software-pipelines TWO samples: both
// dependent gather chains are issued interleaved before any consumption,
// doubling per-warp outstanding memory (tests the latency-bound hypothesis).
// 4096 warps (half of R1), loads stay 32-lane coalesced.

#define D    128
#define TLEN 16

__global__ __launch_bounds__(128) void ttd_transe_kernel(
    const int*   __restrict__ sample,
    const float* __restrict__ entity_emb,
    const float* __restrict__ type_emb,
    const int*   __restrict__ node_type,
    float*       __restrict__ out)
{
    const int warp = (blockIdx.x << 2) + (threadIdx.x >> 5);
    const int lane = threadIdx.x & 31;
    const int sA   = warp * 2;       // sample A
    const int sB   = sA + 1;         // sample B

    // ---- Level 1: both samples' indices (issued together) ----
    const int headA = __ldg(&sample[sA * 3 + 0]);
    const int relA  = __ldg(&sample[sA * 3 + 1]);
    const int headB = __ldg(&sample[sB * 3 + 0]);
    const int relB  = __ldg(&sample[sB * 3 + 1]);

    // ---- Level 2: both node_type gathers + both entity rows in flight ----
    const int ntA = __ldg(&node_type[headA]);
    const int ntB = __ldg(&node_type[headB]);
    const float4* __restrict__ h4A =
        reinterpret_cast<const float4*>(entity_emb) + headA * (D / 4);
    const float4* __restrict__ h4B =
        reinterpret_cast<const float4*>(entity_emb) + headB * (D / 4);
    const float4 hvA = __ldg(&h4A[lane]);
    const float4 hvB = __ldg(&h4B[lane]);

    const float4* __restrict__ mA =
        reinterpret_cast<const float4*>(type_emb)
        + relA * (TLEN * D * D / 4) + ntA * (D * D / 4);
    const float4* __restrict__ mB =
        reinterpret_cast<const float4*>(type_emb)
        + relB * (TLEN * D * D / 4) + ntB * (D * D / 4);

    // ---- Level 3: all six matrix rows issued back-to-back ----
    const float4 a0 = __ldg(&mA[lane]);
    const float4 a1 = __ldg(&mA[32 + lane]);
    const float4 a2 = __ldg(&mA[64 + lane]);
    const float4 b0 = __ldg(&mB[lane]);
    const float4 b1 = __ldg(&mB[32 + lane]);
    const float4 b2 = __ldg(&mB[64 + lane]);

    float sA0 = fmaf(hvA.x, a0.x, fmaf(hvA.y, a0.y, fmaf(hvA.z, a0.z, hvA.w * a0.w)));
    float sA1 = fmaf(hvA.x, a1.x, fmaf(hvA.y, a1.y, fmaf(hvA.z, a1.z, hvA.w * a1.w)));
    float sA2 = fmaf(hvA.x, a2.x, fmaf(hvA.y, a2.y, fmaf(hvA.z, a2.z, hvA.w * a2.w)));
    float sB0 = fmaf(hvB.x, b0.x, fmaf(hvB.y, b0.y, fmaf(hvB.z, b0.z, hvB.w * b0.w)));
    float sB1 = fmaf(hvB.x, b1.x, fmaf(hvB.y, b1.y, fmaf(hvB.z, b1.z, hvB.w * b1.w)));
    float sB2 = fmaf(hvB.x, b2.x, fmaf(hvB.y, b2.y, fmaf(hvB.z, b2.z, hvB.w * b2.w)));

    // Butterfly to 4-lane partials (independent shuffles interleave freely).
    #pragma unroll
    for (int off = 16; off > 2; off >>= 1) {
        sA0 += __shfl_xor_sync(0xFFFFFFFFu, sA0, off);
        sA1 += __shfl_xor_sync(0xFFFFFFFFu, sA1, off);
        sA2 += __shfl_xor_sync(0xFFFFFFFFu, sA2, off);
        sB0 += __shfl_xor_sync(0xFFFFFFFFu, sB0, off);
        sB1 += __shfl_xor_sync(0xFFFFFFFFu, sB1, off);
        sB2 += __shfl_xor_sync(0xFFFFFFFFu, sB2, off);
    }
    sA0 += __shfl_sync(0xFFFFFFFFu, sA0, 1) + __shfl_sync(0xFFFFFFFFu, sA0, 2)
         + __shfl_sync(0xFFFFFFFFu, sA0, 3);
    sA1 += __shfl_sync(0xFFFFFFFFu, sA1, 1) + __shfl_sync(0xFFFFFFFFu, sA1, 2)
         + __shfl_sync(0xFFFFFFFFu, sA1, 3);
    sA2 += __shfl_sync(0xFFFFFFFFu, sA2, 1) + __shfl_sync(0xFFFFFFFFu, sA2, 2)
         + __shfl_sync(0xFFFFFFFFu, sA2, 3);
    sB0 += __shfl_sync(0xFFFFFFFFu, sB0, 1) + __shfl_sync(0xFFFFFFFFu, sB0, 2)
         + __shfl_sync(0xFFFFFFFFu, sB0, 3);
    sB1 += __shfl_sync(0xFFFFFFFFu, sB1, 1) + __shfl_sync(0xFFFFFFFFu, sB1, 2)
         + __shfl_sync(0xFFFFFFFFu, sB1, 3);
    sB2 += __shfl_sync(0xFFFFFFFFu, sB2, 1) + __shfl_sync(0xFFFFFFFFu, sB2, 2)
         + __shfl_sync(0xFFFFFFFFu, sB2, 3);

    if (lane == 0) {
        const float eps = 1e-12f;
        const float aA = sA0 / fmaxf(fabsf(sA0), eps);
        const float bA = sA1 / fmaxf(fabsf(sA1), eps);
        const float cA = sA2 / fmaxf(fabsf(sA2), eps);
        out[sA] = fabsf(aA + bA - cA + 1e-6f);
        const float aB = sB0 / fmaxf(fabsf(sB0), eps);
        const float bB = sB1 / fmaxf(fabsf(sB1), eps);
        const float cB = sB2 / fmaxf(fabsf(sB2), eps);
        out[sB] = fabsf(aB + bB - cB + 1e-6f);
    }
}

extern "C" void kernel_launch(void* const* d_in, const int* in_sizes, int n_in,
                              void* d_out, int out_size)
{
    const int*   sample     = (const int*)  d_in[0];
    const float* entity_emb = (const float*)d_in[1];
    // d_in[2] relation_emb unused
    const float* type_emb   = (const float*)d_in[3];
    const int*   node_type  = (const int*)  d_in[4];
    float* out = (float*)d_out;

    const int B = out_size;                 // 8192
    const int threads = 128;                // 4 warps/block, 2 samples/warp
    const int blocks = B / (2 * (threads / 32));  // 1024

    ttd_transe_kernel<<<blocks, threads>>>(sample, entity_emb, type_emb,
                                           node_type, out);
}

// round 7
// speedup vs baseline: 1.0048x; 1.0048x over previous
#include <cuda_runtime.h>

// Inputs (metadata order):
//   d_in[0] sample       int32  [B,3]      (head, rel, tail)
//   d_in[1] entity_emb   f32    [E,128]
//   d_in[2] relation_emb f32    [R,128]    (unused by the math)
//   d_in[3] type_emb     f32    [T*R, 128*128]
//   d_in[4] node_type    int32  [E]
// Output: f32 [B] scores.
//
// Algebra 1: score uses only he[0..2]; elementwise normalization means we
// only need rows 0..2 of each 128x128 matrix -> 3 dot products per sample.
// Algebra 2: s / max(|s|, 1e-12)  ==  copysign(min(|s|*1e12, 1), s)
//            (sign for |s| >= eps, s*1e12 below) -> no division/MUFU.
//
// Structure: warp-per-sample, single full wave (8192 warps), 1024 CTAs x 256.
// Empirically at the config-invariant floor (R1..R6: 6.6-7.0 us across block
// shapes, cache policies, ILP batching, occupancy 37%-71%).

#define D    128
#define TLEN 16   // T = type_emb rows / R

__global__ __launch_bounds__(256, 8) void ttd_transe_kernel(
    const int*   __restrict__ sample,
    const float* __restrict__ entity_emb,
    const float* __restrict__ type_emb,
    const int*   __restrict__ node_type,
    float*       __restrict__ out)
{
    const int gwarp = (blockIdx.x << 3) + (threadIdx.x >> 5);
    const int lane  = threadIdx.x & 31;

    // Level 1: sample indices (lane-uniform -> broadcast).
    const int head = __ldg(&sample[gwarp * 3 + 0]);
    const int rel  = __ldg(&sample[gwarp * 3 + 1]);

    // Level 2: node_type gather + entity row issued together; the
    // rel-dependent base is formed while node_type is in flight so a single
    // IMAD remains on the critical path after the gather lands.
    const int nt = __ldg(&node_type[head]);
    const float4* __restrict__ h4 =
        reinterpret_cast<const float4*>(entity_emb) + head * (D / 4);
    const float4 hv = __ldg(&h4[lane]);

    const float4* __restrict__ m4 =
        reinterpret_cast<const float4*>(type_emb)
        + rel * (TLEN * D * D / 4) + nt * (D * D / 4);

    // Level 3: matrix rows 0..2 (three coalesced 512B warp loads).
    const float4 r0 = __ldg(&m4[lane]);
    const float4 r1 = __ldg(&m4[32 + lane]);
    const float4 r2 = __ldg(&m4[64 + lane]);

    float s0 = fmaf(hv.x, r0.x, fmaf(hv.y, r0.y, fmaf(hv.z, r0.z, hv.w * r0.w)));
    float s1 = fmaf(hv.x, r1.x, fmaf(hv.y, r1.y, fmaf(hv.z, r1.z, hv.w * r1.w)));
    float s2 = fmaf(hv.x, r2.x, fmaf(hv.y, r2.y, fmaf(hv.z, r2.z, hv.w * r2.w)));

    // Butterfly to 4-lane partials, then lane 0 gathers lanes 1..3 directly.
    #pragma unroll
    for (int off = 16; off > 2; off >>= 1) {
        s0 += __shfl_xor_sync(0xFFFFFFFFu, s0, off);
        s1 += __shfl_xor_sync(0xFFFFFFFFu, s1, off);
        s2 += __shfl_xor_sync(0xFFFFFFFFu, s2, off);
    }
    s0 += __shfl_sync(0xFFFFFFFFu, s0, 1) + __shfl_sync(0xFFFFFFFFu, s0, 2)
        + __shfl_sync(0xFFFFFFFFu, s0, 3);
    s1 += __shfl_sync(0xFFFFFFFFu, s1, 1) + __shfl_sync(0xFFFFFFFFu, s1, 2)
        + __shfl_sync(0xFFFFFFFFu, s1, 3);
    s2 += __shfl_sync(0xFFFFFFFFu, s2, 1) + __shfl_sync(0xFFFFFFFFu, s2, 2)
        + __shfl_sync(0xFFFFFFFFu, s2, 3);

    if (lane == 0) {
        // Exact branchless form of s / max(|s|, 1e-12): no division.
        const float a = copysignf(fminf(fabsf(s0) * 1e12f, 1.0f), s0);
        const float b = copysignf(fminf(fabsf(s1) * 1e12f, 1.0f), s1);
        const float c = copysignf(fminf(fabsf(s2) * 1e12f, 1.0f), s2);
        out[gwarp] = fabsf(a + b - c + 1e-6f);
    }
}

extern "C" void kernel_launch(void* const* d_in, const int* in_sizes, int n_in,
                              void* d_out, int out_size)
{
    const int*   sample     = (const int*)  d_in[0];
    const float* entity_emb = (const float*)d_in[1];
    // d_in[2] relation_emb unused
    const float* type_emb   = (const float*)d_in[3];
    const int*   node_type  = (const int*)  d_in[4];
    float* out = (float*)d_out;

    const int B = out_size;                 // 8192, multiple of 8
    const int threads = 256;                // 8 warps/block, warp per sample
    const int blocks = B / 8;               // 1024

    ttd_transe_kernel<<<blocks, threads>>>(sample, entity_emb, type_emb,
                                           node_type, out);
}